// round 1
// baseline (speedup 1.0000x reference)
#include <cuda_runtime.h>
#include <stdint.h>

#define NN      16384
#define EE      524288
#define DD      128
#define HH      256
#define CC      10
#define GG      64
#define WPR     512          // bitmask words per row (16384/32)
#define CAP     160          // max neighbors per row (Poisson(32) tail << 1e-18 at 96)

// ---------------- scratch (device globals; no allocation allowed) ----------------
__device__ uint32_t g_bm[(size_t)NN * WPR];        // 32 MB adjacency bitmask
__device__ int      g_nbr[(size_t)NN * CAP];       // CSR neighbor lists (sorted)
__device__ int      g_deg[NN];
__device__ float    g_dis[NN];
__device__ float    g_xd  [(size_t)NN * DD];       // dis[j]*x[j]
__device__ float    g_agg1[(size_t)NN * DD];
__device__ float    g_hd1 [(size_t)NN * HH];       // dis*relu(agg1@W1+b1)
__device__ float    g_agg2[(size_t)NN * HH];
__device__ float    g_h2  [(size_t)NN * HH];       // relu(agg2@W2+b2)
__device__ int      g_segstart[GG + 1];

// ---------------- kernels ----------------

__global__ void zero_bm_kernel() {
    const int n4 = NN * WPR / 4;  // 2,097,152 uint4
    uint4 z = make_uint4(0, 0, 0, 0);
    for (int i = blockIdx.x * blockDim.x + threadIdx.x; i < n4; i += gridDim.x * blockDim.x)
        reinterpret_cast<uint4*>(g_bm)[i] = z;
}

__global__ void scatter_kernel(const int* __restrict__ ei) {
    int idx = blockIdx.x * blockDim.x + threadIdx.x;
    if (idx < EE) {
        int s = ei[idx];
        int d = ei[EE + idx];
        atomicOr(&g_bm[(size_t)s * WPR + (d >> 5)], 1u << (d & 31));
    } else if (idx < EE + NN) {
        int i = idx - EE;
        atomicOr(&g_bm[(size_t)i * WPR + (i >> 5)], 1u << (i & 31));
    }
}

// warp per row: scan 512 bitmask words, emit sorted neighbor list + degree
__global__ void build_csr_kernel() {
    int wid  = (blockIdx.x * blockDim.x + threadIdx.x) >> 5;
    int lane = threadIdx.x & 31;
    if (wid >= NN) return;
    const uint32_t* row = g_bm + (size_t)wid * WPR;
    int* nbr = g_nbr + (size_t)wid * CAP;
    int cnt = 0;
    for (int w0 = 0; w0 < WPR; w0 += 32) {
        uint32_t bits = row[w0 + lane];
        int pc = __popc(bits);
        int incl = pc;
        #pragma unroll
        for (int o = 1; o < 32; o <<= 1) {
            int v = __shfl_up_sync(0xFFFFFFFFu, incl, o);
            if (lane >= o) incl += v;
        }
        int base = cnt + incl - pc;
        while (bits) {
            int b = __ffs(bits) - 1;
            bits &= bits - 1;
            if (base < CAP) nbr[base] = (w0 + lane) * 32 + b;
            base++;
        }
        cnt += __shfl_sync(0xFFFFFFFFu, incl, 31);
    }
    if (lane == 0) {
        int c = cnt < 1 ? 1 : cnt;
        g_deg[wid] = cnt < CAP ? cnt : CAP;
        g_dis[wid] = rsqrtf((float)c);
    }
}

__global__ void scale_x_kernel(const float* __restrict__ x) {
    const int n4 = NN * DD / 4;   // 32 float4 per row
    const float4* x4 = reinterpret_cast<const float4*>(x);
    float4* o4 = reinterpret_cast<float4*>(g_xd);
    for (int i = blockIdx.x * blockDim.x + threadIdx.x; i < n4; i += gridDim.x * blockDim.x) {
        float s = g_dis[i >> 5];
        float4 v = x4[i];
        v.x *= s; v.y *= s; v.z *= s; v.w *= s;
        o4[i] = v;
    }
}

// warp per row, D=128: lane handles one float4 of the feature vector
__global__ void agg1_kernel() {
    int row  = (blockIdx.x * blockDim.x + threadIdx.x) >> 5;
    int lane = threadIdx.x & 31;
    if (row >= NN) return;
    const float4* xd4 = reinterpret_cast<const float4*>(g_xd);
    const int* nbr = g_nbr + (size_t)row * CAP;
    int cnt = g_deg[row];
    float4 acc = make_float4(0.f, 0.f, 0.f, 0.f);
    for (int t0 = 0; t0 < cnt; t0 += 32) {
        int j = (t0 + lane < cnt) ? nbr[t0 + lane] : 0;
        int m = min(32, cnt - t0);
        for (int k = 0; k < m; k++) {
            int jj = __shfl_sync(0xFFFFFFFFu, j, k);
            float4 v = xd4[(size_t)jj * 32 + lane];
            acc.x += v.x; acc.y += v.y; acc.z += v.z; acc.w += v.w;
        }
    }
    float s = g_dis[row];
    acc.x *= s; acc.y *= s; acc.z *= s; acc.w *= s;
    reinterpret_cast<float4*>(g_agg1)[(size_t)row * 32 + lane] = acc;
}

// warp per row, H=256: lane handles two float4
__global__ void agg2_kernel() {
    int row  = (blockIdx.x * blockDim.x + threadIdx.x) >> 5;
    int lane = threadIdx.x & 31;
    if (row >= NN) return;
    const float4* h4 = reinterpret_cast<const float4*>(g_hd1);
    const int* nbr = g_nbr + (size_t)row * CAP;
    int cnt = g_deg[row];
    float4 a0 = make_float4(0.f, 0.f, 0.f, 0.f);
    float4 a1 = make_float4(0.f, 0.f, 0.f, 0.f);
    for (int t0 = 0; t0 < cnt; t0 += 32) {
        int j = (t0 + lane < cnt) ? nbr[t0 + lane] : 0;
        int m = min(32, cnt - t0);
        for (int k = 0; k < m; k++) {
            int jj = __shfl_sync(0xFFFFFFFFu, j, k);
            float4 v0 = h4[(size_t)jj * 64 + lane];
            float4 v1 = h4[(size_t)jj * 64 + 32 + lane];
            a0.x += v0.x; a0.y += v0.y; a0.z += v0.z; a0.w += v0.w;
            a1.x += v1.x; a1.y += v1.y; a1.z += v1.z; a1.w += v1.w;
        }
    }
    float s = g_dis[row];
    a0.x *= s; a0.y *= s; a0.z *= s; a0.w *= s;
    a1.x *= s; a1.y *= s; a1.z *= s; a1.w *= s;
    float4* o4 = reinterpret_cast<float4*>(g_agg2);
    o4[(size_t)row * 64 + lane]      = a0;
    o4[(size_t)row * 64 + 32 + lane] = a1;
}

// 128x128x8 register-tiled SGEMM, 8x8 per thread, fused bias + relu (+ dis scale)
// M=16384, Nout=256 fixed; K templated via arg.
template <bool SCALE>
__device__ __forceinline__ void gemm_body(const float* __restrict__ A,
                                          const float* __restrict__ W,
                                          const float* __restrict__ bias,
                                          float* __restrict__ C, int K) {
    __shared__ float As[8][128];
    __shared__ float Bs[8][128];
    const int Nout = 256;
    int tid = threadIdx.x;
    int tx = tid & 15, ty = tid >> 4;
    int rowBase = blockIdx.y * 128;
    int colBase = blockIdx.x * 128;

    float acc[8][8];
    #pragma unroll
    for (int i = 0; i < 8; i++)
        #pragma unroll
        for (int j = 0; j < 8; j++) acc[i][j] = 0.f;

    int arow = tid >> 1;          // 0..127
    int acol = (tid & 1) * 4;     // 0 or 4
    int brow = tid >> 5;          // 0..7
    int bcol = (tid & 31) * 4;    // 0..124

    for (int k0 = 0; k0 < K; k0 += 8) {
        float4 av = *reinterpret_cast<const float4*>(A + (size_t)(rowBase + arow) * K + k0 + acol);
        float4 bv = *reinterpret_cast<const float4*>(W + (size_t)(k0 + brow) * Nout + colBase + bcol);
        As[acol + 0][arow] = av.x;
        As[acol + 1][arow] = av.y;
        As[acol + 2][arow] = av.z;
        As[acol + 3][arow] = av.w;
        *reinterpret_cast<float4*>(&Bs[brow][bcol]) = bv;
        __syncthreads();
        #pragma unroll
        for (int k = 0; k < 8; k++) {
            float4 a0 = *reinterpret_cast<float4*>(&As[k][ty * 4]);
            float4 a1 = *reinterpret_cast<float4*>(&As[k][64 + ty * 4]);
            float4 b0 = *reinterpret_cast<float4*>(&Bs[k][tx * 4]);
            float4 b1 = *reinterpret_cast<float4*>(&Bs[k][64 + tx * 4]);
            float ar[8] = {a0.x, a0.y, a0.z, a0.w, a1.x, a1.y, a1.z, a1.w};
            float br[8] = {b0.x, b0.y, b0.z, b0.w, b1.x, b1.y, b1.z, b1.w};
            #pragma unroll
            for (int i = 0; i < 8; i++)
                #pragma unroll
                for (int j = 0; j < 8; j++) acc[i][j] += ar[i] * br[j];
        }
        __syncthreads();
    }

    #pragma unroll
    for (int i = 0; i < 8; i++) {
        int row = rowBase + ((i < 4) ? (ty * 4 + i) : (64 + ty * 4 + i - 4));
        float s = SCALE ? g_dis[row] : 1.f;
        #pragma unroll
        for (int j = 0; j < 8; j++) {
            int col = colBase + ((j < 4) ? (tx * 4 + j) : (64 + tx * 4 + j - 4));
            float v = acc[i][j] + bias[col];
            v = fmaxf(v, 0.f);
            if (SCALE) v *= s;
            C[(size_t)row * Nout + col] = v;
        }
    }
}

__global__ void __launch_bounds__(256) gemm1_kernel(const float* __restrict__ W1,
                                                    const float* __restrict__ b1) {
    gemm_body<true>(g_agg1, W1, b1, g_hd1, DD);
}

__global__ void __launch_bounds__(256) gemm2_kernel(const float* __restrict__ W2,
                                                    const float* __restrict__ b2) {
    gemm_body<false>(g_agg2, W2, b2, g_h2, HH);
}

__global__ void segstart_kernel(const int* __restrict__ batch) {
    int g = threadIdx.x;
    if (g > GG) return;
    if (g == GG) { g_segstart[GG] = NN; return; }
    int lo = 0, hi = NN;
    while (lo < hi) {
        int mid = (lo + hi) >> 1;
        if (batch[mid] < g) lo = mid + 1; else hi = mid;
    }
    g_segstart[g] = lo;
}

// block per graph: deterministic segment-mean + tiny classifier matvec
__global__ void __launch_bounds__(256) pool_classify_kernel(const float* __restrict__ Wc,
                                                            const float* __restrict__ bc,
                                                            float* __restrict__ out) {
    int g = blockIdx.x;
    int t = threadIdx.x;
    int s = g_segstart[g], e = g_segstart[g + 1];
    float sum = 0.f;
    for (int n = s; n < e; n++) sum += g_h2[(size_t)n * HH + t];
    float cnt = (float)max(e - s, 1);
    float pv = sum / cnt;

    float part[CC];
    const float* wr = Wc + t * CC;   // Wc is [H, C] row-major
    #pragma unroll
    for (int c = 0; c < CC; c++) part[c] = pv * wr[c];
    #pragma unroll
    for (int o = 16; o > 0; o >>= 1)
        #pragma unroll
        for (int c = 0; c < CC; c++) part[c] += __shfl_down_sync(0xFFFFFFFFu, part[c], o);

    __shared__ float red[8][CC];
    if ((t & 31) == 0)
        #pragma unroll
        for (int c = 0; c < CC; c++) red[t >> 5][c] = part[c];
    __syncthreads();
    if (t < CC) {
        float o = bc[t];
        #pragma unroll
        for (int w = 0; w < 8; w++) o += red[w][t];
        out[g * CC + t] = o;
    }
}

// ---------------- launch ----------------
extern "C" void kernel_launch(void* const* d_in, const int* in_sizes, int n_in,
                              void* d_out, int out_size) {
    const float* x   = (const float*)d_in[0];
    const int*   ei  = (const int*)  d_in[1];
    const int*   bat = (const int*)  d_in[2];
    const float* W1  = (const float*)d_in[3];
    const float* b1  = (const float*)d_in[4];
    const float* W2  = (const float*)d_in[5];
    const float* b2  = (const float*)d_in[6];
    const float* Wc  = (const float*)d_in[7];
    const float* bc  = (const float*)d_in[8];
    float* out = (float*)d_out;

    zero_bm_kernel<<<2048, 256>>>();
    scatter_kernel<<<(EE + NN + 255) / 256, 256>>>(ei);
    build_csr_kernel<<<NN / 8, 256>>>();
    scale_x_kernel<<<2048, 256>>>(x);
    agg1_kernel<<<NN / 8, 256>>>();
    gemm1_kernel<<<dim3(2, 128), 256>>>(W1, b1);
    agg2_kernel<<<NN / 8, 256>>>();
    gemm2_kernel<<<dim3(2, 128), 256>>>(W2, b2);
    segstart_kernel<<<1, GG + 1>>>(bat);
    pool_classify_kernel<<<GG, 256>>>(Wc, bc, out);
}